// round 4
// baseline (speedup 1.0000x reference)
#include <cuda_runtime.h>
#include <cub/cub.cuh>

#define MAXN 1600000
#define MAXB 8
#define PRE_K 6000
#define POST_K 1000
#define MASKW 94            // ceil(6000/64)
#define NEGV  -1000000000.0f
#define NEG_HALF -500000000.0f

// ---------------- static device scratch (no allocations allowed) ----------------
__device__ unsigned long long g_keys_in[MAXN];
__device__ unsigned long long g_keys_out[MAXN];
__device__ unsigned int       g_vals_in[MAXN];
__device__ unsigned int       g_vals_out[MAXN];
__device__ float4             g_boxes[MAXN];
__device__ float              g_score[MAXN];
__device__ int                g_segstart[MAXB + 1];
__device__ float4             g_cboxes[MAXB * PRE_K];
__device__ float              g_cscore[MAXB * PRE_K];
__device__ int                g_cidx[MAXB * PRE_K];
__device__ int                g_rowany[MAXB * PRE_K];
__device__ unsigned long long g_mask[(size_t)MAXB * PRE_K * MASKW]; // ~36MB, .bss zero-init
__device__ int                g_kept[MAXB * POST_K];
__device__ unsigned char      g_temp[64u << 20];                    // cub temp storage

// ---------------- XLA-exact sigmoid: 0.5 + 0.5*tanh(0.5x), fast-tanh poly ------
__device__ __forceinline__ float xla_tanh(float x) {
    float ax = fabsf(x);
    float xc = fminf(fmaxf(x, -7.99881172180175781f), 7.99881172180175781f);
    float x2 = __fmul_rn(xc, xc);
    float p = fmaf(x2, -2.76076847742355e-16f, 2.00018790482477e-13f);
    p = fmaf(p, x2, -8.60467152213735e-11f);
    p = fmaf(p, x2,  5.12229709037114e-08f);
    p = fmaf(p, x2,  1.48572235717979e-05f);
    p = fmaf(p, x2,  6.37261928875436e-04f);
    p = fmaf(p, x2,  4.89352455891786e-03f);
    float num = __fmul_rn(xc, p);
    float q = fmaf(x2, 1.19825839466702e-06f, 1.18534705686654e-04f);
    q = fmaf(q, x2, 2.26843463243900e-03f);
    q = fmaf(q, x2, 4.89352518554385e-03f);
    float r = __fdiv_rn(num, q);
    return (ax < 0.0004f) ? x : r;
}

__device__ __forceinline__ float xla_sigmoid(float x) {
    float t = xla_tanh(__fmul_rn(0.5f, x));
    return __fadd_rn(__fmul_rn(0.5f, t), 0.5f);
}

// ---------------- kernel 1: decode boxes, score, build sort keys ---------------
__global__ __launch_bounds__(256)
void k_decode(const float4* __restrict__ anchors, const int* __restrict__ bidx,
              const int* __restrict__ sizes, const float* __restrict__ logits,
              const float4* __restrict__ deltas, int N)
{
    int i = blockIdx.x * blockDim.x + threadIdx.x;
    if (i >= N) return;
    float4 a = anchors[i];
    float4 d = deltas[i];
    int b = bidx[i];
    float H = (float)sizes[2 * b];
    float W = (float)sizes[2 * b + 1];

    // exact op order of reference, no FMA contraction
    float aw = __fsub_rn(a.z, a.x);
    float ah = __fsub_rn(a.w, a.y);
    float ax = __fadd_rn(a.x, __fmul_rn(0.5f, aw));
    float ay = __fadd_rn(a.y, __fmul_rn(0.5f, ah));
    float px = __fadd_rn(ax, __fmul_rn(d.x, aw));
    float py = __fadd_rn(ay, __fmul_rn(d.y, ah));
    float twc = fminf(fmaxf(d.z, -10.0f), 10.0f);
    float thc = fminf(fmaxf(d.w, -10.0f), 10.0f);
    float pw = __fmul_rn(aw, expf(twc));   // expf == libdevice __nv_expf == XLA exp
    float ph = __fmul_rn(ah, expf(thc));
    float x1 = __fsub_rn(px, __fmul_rn(0.5f, pw));
    float y1 = __fsub_rn(py, __fmul_rn(0.5f, ph));
    float x2 = __fadd_rn(px, __fmul_rn(0.5f, pw));
    float y2 = __fadd_rn(py, __fmul_rn(0.5f, ph));
    float Wm1 = __fsub_rn(W, 1.0f);
    float Hm1 = __fsub_rn(H, 1.0f);
    x1 = fminf(fmaxf(x1, 0.0f), Wm1);
    y1 = fminf(fmaxf(y1, 0.0f), Hm1);
    x2 = fminf(fmaxf(x2, 0.0f), Wm1);
    y2 = fminf(fmaxf(y2, 0.0f), Hm1);
    bool valid = (__fsub_rn(x2, x1) >= 16.0f) && (__fsub_rn(y2, y1) >= 16.0f);

    float fg = xla_sigmoid(logits[i]);
    float sc = valid ? fg : NEGV;

    g_boxes[i] = make_float4(x1, y1, x2, y2);
    g_score[i] = sc;

    unsigned ub = __float_as_uint(sc);
    ub = (ub & 0x80000000u) ? ~ub : (ub | 0x80000000u);    // float -> ascending uint
    g_keys_in[i] = ((unsigned long long)(unsigned)b << 32) | (unsigned)(~ub);
    g_vals_in[i] = (unsigned)i;
}

// ---------------- kernel 2: per-image segment starts (batch_indices sorted) ----
__global__ void k_segstart(const int* __restrict__ bi, int N, int B)
{
    int t = threadIdx.x;
    if (t > B) return;
    if (t == B) { g_segstart[B] = N; return; }
    int lo = 0, hi = N;
    while (lo < hi) { int mid = (lo + hi) >> 1; if (bi[mid] < t) lo = mid + 1; else hi = mid; }
    g_segstart[t] = lo;
}

// ---------------- kernel 3: gather sorted top-PRE_K per image (+ clear rowany) -
__global__ __launch_bounds__(256)
void k_gather(int B)
{
    int t = blockIdx.x * blockDim.x + threadIdx.x;
    if (t >= B * PRE_K) return;
    g_rowany[t] = 0;
    int b = t / PRE_K, p = t - b * PRE_K;
    int s = g_segstart[b], e = g_segstart[b + 1];
    if (s + p < e) {
        int gi = (int)g_vals_out[s + p];
        g_cidx[t] = gi;
        g_cscore[t] = g_score[gi];
        g_cboxes[t] = g_boxes[gi];
    } else {
        g_cidx[t] = 0; g_cscore[t] = NEGV; g_cboxes[t] = make_float4(0, 0, 0, 0);
    }
}

// ---------------- kernel 4: IoU suppression bitmask (upper triangle) -----------
__global__ __launch_bounds__(64)
void k_mask()
{
    int b = blockIdx.z, rb = blockIdx.y, cb = blockIdx.x;
    if (cb < rb) return;                       // lower triangle stays zero (bss)
    __shared__ float4 sbx[64];
    __shared__ float  sar[64];
    int t = threadIdx.x;
    int cbase = cb * 64;
    int ncol = min(64, PRE_K - cbase);
    if (t < ncol) {
        float4 v = g_cboxes[b * PRE_K + cbase + t];
        sbx[t] = v;
        sar[t] = __fmul_rn(__fsub_rn(v.z, v.x), __fsub_rn(v.w, v.y));
    }
    __syncthreads();
    int i = rb * 64 + t;
    if (i >= PRE_K) return;
    float4 bi_ = g_cboxes[b * PRE_K + i];
    float ai = __fmul_rn(__fsub_rn(bi_.z, bi_.x), __fsub_rn(bi_.w, bi_.y));
    unsigned long long bits = 0;
    for (int j = 0; j < ncol; j++) {
        float4 bj = sbx[j];
        float ix1 = fmaxf(bi_.x, bj.x), iy1 = fmaxf(bi_.y, bj.y);
        float ix2 = fminf(bi_.z, bj.z), iy2 = fminf(bi_.w, bj.w);
        float inter = __fmul_rn(fmaxf(__fsub_rn(ix2, ix1), 0.0f),
                                fmaxf(__fsub_rn(iy2, iy1), 0.0f));
        float denom = __fadd_rn(__fsub_rn(__fadd_rn(sar[j], ai), inter), 1e-9f);
        if (__fdiv_rn(inter, denom) > 0.7f) bits |= 1ull << j;
    }
    g_mask[((size_t)b * PRE_K + i) * MASKW + cb] = bits;
    unsigned long long nonself = bits;
    if (cb == rb) nonself &= ~(1ull << (i - cbase));
    if (nonself) g_rowany[b * PRE_K + i] = 1;   // benign race: all writers store 1
}

// ---------------- kernel 5: sequential greedy NMS (one warp per image) ---------
__device__ __forceinline__ unsigned long long shfl64(unsigned long long v, int src) {
    return __shfl_sync(0xffffffffu, v, src);
}

__global__ __launch_bounds__(32)
void k_nms()
{
    int b = blockIdx.x;
    int lane = threadIdx.x;
    __shared__ float sscore[PRE_K];
    __shared__ unsigned long long srany[MASKW];
    const int base = b * PRE_K;
    for (int i = lane; i < PRE_K; i += 32) sscore[i] = g_cscore[base + i];
    for (int w = lane; w < MASKW; w += 32) {
        unsigned long long bits = 0;
        int nrows = min(64, PRE_K - w * 64);
        for (int r = 0; r < nrows; r++)
            if (g_rowany[base + w * 64 + r]) bits |= 1ull << r;
        srany[w] = bits;
    }
    __syncwarp();

    unsigned long long r0 = 0, r1 = 0, r2 = 0;   // removed bitmask: lane owns words lane, lane+32, lane+64
    const unsigned long long* mrow = g_mask + (size_t)base * MASKW;
    const int outb = b * POST_K;
    int i = 0, nk = 0;
    while (i < PRE_K && nk < POST_K) {
        int w = i >> 6;
        int slot = w >> 5, owner = w & 31;
        unsigned long long myw = (slot == 0) ? r0 : ((slot == 1) ? r1 : r2);
        if ((i & 63) == 0 && nk + 64 <= POST_K && i + 64 <= PRE_K && srany[w] == 0ull) {
            unsigned long long word = shfl64(myw, owner);
            if (word == 0ull && sscore[i + 63] > NEG_HALF) {
                // fast path: all 64 survive, nothing suppressed, state unchanged
                g_kept[outb + nk + lane] = i + lane;
                g_kept[outb + nk + 32 + lane] = i + 32 + lane;
                nk += 64; i += 64; continue;
            }
        }
        unsigned bit = (unsigned)((myw >> (i & 63)) & 1ull);
        bit = __shfl_sync(0xffffffffu, bit, owner);
        if (!bit) {
            if (sscore[i] <= NEG_HALF) break;    // sorted: everything after is invalid
            if (lane == 0) g_kept[outb + nk] = i;
            nk++;
            if ((srany[w] >> (i & 63)) & 1ull) { // this row suppresses someone: OR its mask
                const unsigned long long* m = mrow + (size_t)i * MASKW;
                r0 |= m[lane];
                int w1 = lane + 32; if (w1 < MASKW) r1 |= m[w1];
                int w2 = lane + 64; if (w2 < MASKW) r2 |= m[w2];
            }
        }
        i++;
    }
    for (int t = nk + lane; t < POST_K; t += 32) g_kept[outb + t] = -1;
}

// ---------------- kernel 6: write outputs --------------------------------------
__global__ __launch_bounds__(256)
void k_out(const float* __restrict__ logits, const float4* __restrict__ deltas,
           float* __restrict__ out, int B)
{
    int t = blockIdx.x * blockDim.x + threadIdx.x;
    int P = B * POST_K;
    if (t >= P) return;
    int b = t / POST_K;
    int j = g_kept[t];
    float4 pb = make_float4(0, 0, 0, 0), dl = make_float4(0, 0, 0, 0);
    float ob = 0.0f, bi = -1.0f, okf = 0.0f;
    if (j >= 0) {
        int gi = g_cidx[b * PRE_K + j];
        pb = g_cboxes[b * PRE_K + j];
        ob = logits[gi];
        dl = deltas[gi];
        bi = (float)b;
        okf = 1.0f;
    }
    // layout: props[4P] | bidx[P] | obj[P] | deltas[4P] | keep_ok[P]
    ((float4*)out)[t] = pb;
    out[4 * P + t] = bi;
    out[5 * P + t] = ob;
    ((float4*)(out + 6 * P))[t] = dl;
    out[10 * P + t] = okf;
}

// ---------------- launcher ------------------------------------------------------
extern "C" void kernel_launch(void* const* d_in, const int* in_sizes, int n_in,
                              void* d_out, int out_size)
{
    const float4* anchors = (const float4*)d_in[0];
    const int*    bidx    = (const int*)d_in[1];
    const int*    sizes   = (const int*)d_in[2];
    const float*  logits  = (const float*)d_in[3];
    const float4* deltas  = (const float4*)d_in[4];
    float* out = (float*)d_out;

    int N = in_sizes[0] / 4;
    int B = in_sizes[2] / 2;
    if (N > MAXN) N = MAXN;
    if (B > MAXB) B = MAXB;

    k_decode<<<(N + 255) / 256, 256>>>(anchors, bidx, sizes, logits, deltas, N);
    k_segstart<<<1, 32>>>(bidx, N, B);

    void *pkin = nullptr, *pkout = nullptr, *pvin = nullptr, *pvout = nullptr, *ptmp = nullptr;
    cudaGetSymbolAddress(&pkin,  g_keys_in);
    cudaGetSymbolAddress(&pkout, g_keys_out);
    cudaGetSymbolAddress(&pvin,  g_vals_in);
    cudaGetSymbolAddress(&pvout, g_vals_out);
    cudaGetSymbolAddress(&ptmp,  g_temp);

    size_t tb = 0;
    cub::DeviceRadixSort::SortPairs(nullptr, tb,
        (const unsigned long long*)pkin, (unsigned long long*)pkout,
        (const unsigned*)pvin, (unsigned*)pvout, N, 0, 35);
    cub::DeviceRadixSort::SortPairs(ptmp, tb,
        (const unsigned long long*)pkin, (unsigned long long*)pkout,
        (const unsigned*)pvin, (unsigned*)pvout, N, 0, 35);

    k_gather<<<(B * PRE_K + 255) / 256, 256>>>(B);
    dim3 mg(MASKW, MASKW, B);
    k_mask<<<mg, 64>>>();
    k_nms<<<B, 32>>>();
    k_out<<<(B * POST_K + 255) / 256, 256>>>(logits, deltas, out, B);
}